// round 7
// baseline (speedup 1.0000x reference)
#include <cuda_runtime.h>
#include <cuda_fp16.h>
#include <cstdint>

#define NBLK   128
#define NTHR   256
#define TSTEPS 512
#define OUTN   (512*128*512)

// ---- lstm smem byte offsets ------------------------------------------------
#define SM_BIAS 0         // 32 f32
#define SM_ZSH  128       // 16*132*4 = 8448
#define SM_W    8576      // B frags: [l*2+half][64 sg][2 nt][32 lane]*8B = 131072
#define SM_A    139648    // 4 bufs * 16KB
#define SM_TOT  205184

// ---- x0gemm smem -----------------------------------------------------------
#define XW_BYTES 131072   // [half][32 sg][8 nt][32 lane]*8B
#define X0_TOT   (XW_BYTES + 65536)

// ---- persistent state (device globals) -------------------------------------
__device__ __align__(16) __half g_x[(size_t)TSTEPS*128*512];
__device__ __align__(16) float  g_z0x[(size_t)TSTEPS*2048*128];   // [t][c_g][n]
__device__ __align__(16) __half g_hst[2][2][128*512];   // [layer][pingpong]
__device__ __align__(16) __half g_mid[2][128*512];      // [pingpong]
__device__ unsigned g_bar_count = 0;
__device__ volatile unsigned g_bar_gen = 0;

// ---- grid barrier ----------------------------------------------------------
__device__ __forceinline__ void grid_barrier() {
    __syncthreads();
    if (threadIdx.x == 0) {
        __threadfence();
        unsigned gen = g_bar_gen;
        if (atomicAdd(&g_bar_count, 1u) == NBLK - 1) {
            g_bar_count = 0;
            __threadfence();
            g_bar_gen = gen + 1;
        } else {
            while (g_bar_gen == gen) { __nanosleep(20); }
        }
        __threadfence();
    }
    __syncthreads();
}

// ---- asm helpers -----------------------------------------------------------
__device__ __forceinline__ void cp16(uint32_t s, const void* g) {
    asm volatile("cp.async.cg.shared.global [%0], [%1], 16;" :: "r"(s), "l"(g));
}
__device__ __forceinline__ void cp_commit() { asm volatile("cp.async.commit_group;"); }
template<int N> __device__ __forceinline__ void cp_wait() {
    asm volatile("cp.async.wait_group %0;" :: "n"(N));
}
__device__ __forceinline__ void ldm4(uint32_t (&a)[4], uint32_t addr) {
    asm volatile("ldmatrix.sync.aligned.m8n8.x4.shared.b16 {%0,%1,%2,%3}, [%4];"
                 : "=r"(a[0]), "=r"(a[1]), "=r"(a[2]), "=r"(a[3]) : "r"(addr));
}
__device__ __forceinline__ void mma(float (&d)[4], const uint32_t (&a)[4],
                                    uint32_t b0, uint32_t b1) {
    asm volatile("mma.sync.aligned.m16n8k16.row.col.f32.f16.f16.f32 "
        "{%0,%1,%2,%3}, {%4,%5,%6,%7}, {%8,%9}, {%0,%1,%2,%3};"
        : "+f"(d[0]), "+f"(d[1]), "+f"(d[2]), "+f"(d[3])
        : "r"(a[0]), "r"(a[1]), "r"(a[2]), "r"(a[3]), "r"(b0), "r"(b1));
}
__device__ __forceinline__ void stcg4(void* p, uint32_t a) {
    asm volatile("st.global.cg.b32 [%0], %1;" :: "l"(p), "r"(a));
}
__device__ __forceinline__ void stcg16(void* p, unsigned short v) {
    asm volatile("st.global.cg.u16 [%0], %1;" :: "l"(p), "h"(v));
}

__device__ __forceinline__ float sigm(float x) { return 1.0f / (1.0f + __expf(-x)); }

__device__ __forceinline__ void h2split(float v, unsigned short& hi, unsigned short& lo) {
    __half h = __float2half_rn(v);
    float r = v - __half2float(h);
    __half l2 = __float2half_rn(r);
    hi = __half_as_ushort(h);
    lo = __half_as_ushort(l2);
}

// ---- warp-private A staging: warp w stages its own 16-row band -------------
__device__ __forceinline__ void stage_w(const __half* s0, const __half* s1,
                                        int c, uint32_t abase, int w, int lane) {
    const __half* p = (c < 8) ? s0 : s1;
    int coff = (c & 7) << 6;
    uint32_t dst = abase + (c & 3) * 16384;
    int rq = lane >> 3, cq = lane & 7;
#pragma unroll
    for (int jj = 0; jj < 4; ++jj) {
        int row = w * 16 + jj * 4 + rq;
        uint32_t d = dst + row * 128 + ((cq ^ (row & 7)) << 4);
        cp16(d, p + (size_t)row * 512 + coff + cq * 8);
    }
}

// ---- one layer phase -------------------------------------------------------
__device__ __forceinline__ void phase(
    int l, int t, int blk, int nchunks,
    const __half* s0, const __half* s1,
    const float* __restrict__ zx,               // phase0: Z0x[t] base, else null
    __half* hdst, __half* mdst,
    char* sm, uint32_t smb,
    float (&creg)[2],
    const float* __restrict__ masks, float* __restrict__ out)
{
    int tid = threadIdx.x, w = tid >> 5, lane = tid & 31;
    int sub = lane >> 3, lrow = lane & 7;
    const uint2* bf = (const uint2*)(sm + SM_W);
    uint32_t abase = smb + SM_A;

    float acc[2][4] = {};

#pragma unroll
    for (int c = 0; c < 4; ++c) { stage_w(s0, s1, c, abase, w, lane); cp_commit(); }

#pragma unroll 1
    for (int i = 0; i < nchunks; ++i) {
        cp_wait<3>();
        uint32_t ab = abase + (i & 3) * 16384;
#pragma unroll
        for (int ks = 0; ks < 4; ++ks) {
            uint32_t Ah[4];
            int r = w * 16 + ((sub & 1) << 3) + lrow;
            uint32_t aoff = r * 128 + (((2 * ks + (sub >> 1)) ^ (r & 7)) << 4);
            ldm4(Ah, ab + aoff);
            int sg = i * 4 + ks;
            uint2 Bh0 = bf[(((l * 2 + 0) * 64 + sg) * 2 + 0) * 32 + lane];
            uint2 Bh1 = bf[(((l * 2 + 0) * 64 + sg) * 2 + 1) * 32 + lane];
            uint2 Bl0 = bf[(((l * 2 + 1) * 64 + sg) * 2 + 0) * 32 + lane];
            uint2 Bl1 = bf[(((l * 2 + 1) * 64 + sg) * 2 + 1) * 32 + lane];
            mma(acc[0], Ah, Bh0.x, Bh0.y);
            mma(acc[1], Ah, Bh1.x, Bh1.y);
            mma(acc[0], Ah, Bl0.x, Bl0.y);
            mma(acc[1], Ah, Bl1.x, Bl1.y);
        }
        if (i + 4 < nchunks) stage_w(s0, s1, i + 4, abase, w, lane);
        cp_commit();
    }

    // z -> smem transpose (warp writes only its own 16 m-rows: disjoint)
    float* zsh = (float*)(sm + SM_ZSH);
#pragma unroll
    for (int nt = 0; nt < 2; ++nt) {
        int m0 = w * 16 + (lane >> 2);
        int n0 = nt * 8 + (lane & 3) * 2;
        zsh[n0 * 132 + m0]           = acc[nt][0];
        zsh[(n0 + 1) * 132 + m0]     = acc[nt][1];
        zsh[n0 * 132 + m0 + 8]       = acc[nt][2];
        zsh[(n0 + 1) * 132 + m0 + 8] = acc[nt][3];
    }
    __syncthreads();

    // gates: thread -> (n = tid&127, unit pair uh = tid>>7)
    int n = tid & 127, uh = tid >> 7;
    float m  = __ldg(masks + t * 128 + n);
    float mn = (t < TSTEPS - 1) ? __ldg(masks + (t + 1) * 128 + n) : 0.f;
    const float* bs = (const float*)(sm + SM_BIAS) + l * 16;
    unsigned short sh[2], th[2];
    float hv[2];
#pragma unroll
    for (int v = 0; v < 2; ++v) {
        int u = uh * 2 + v;
        float zi = zsh[(0  + u) * 132 + n] + bs[u];
        float zf = zsh[(4  + u) * 132 + n] + bs[4 + u];
        float zg = zsh[(8  + u) * 132 + n] + bs[8 + u];
        float zo = zsh[(12 + u) * 132 + n] + bs[12 + u];
        if (zx) {
            int cg = blk * 4 + u;
            zi += __ldcg(zx + (0 * 512 + cg) * 128 + n);
            zf += __ldcg(zx + (1 * 512 + cg) * 128 + n);
            zg += __ldcg(zx + (2 * 512 + cg) * 128 + n);
            zo += __ldcg(zx + (3 * 512 + cg) * 128 + n);
        }
        float ii = sigm(zi), ff = sigm(zf), oo = sigm(zo);
        float gg = tanhf(zg);
        float cc = ff * (creg[v] * m) + ii * gg;
        float hh = oo * tanhf(cc);
        creg[v] = cc;
        hv[v] = hh;
        sh[v] = __half_as_ushort(__float2half_rn(hh * mn));
        if (l == 0) th[v] = __half_as_ushort(__float2half_rn(hh));
    }
    size_t base = (size_t)n * 512 + blk * 4 + uh * 2;
    stcg4(hdst + base, sh[0] | ((uint32_t)sh[1] << 16));
    if (l == 0) {
        stcg4(mdst + base, th[0] | ((uint32_t)th[1] << 16));
    } else {
        *(float2*)(out + (size_t)t * 65536 + base) = make_float2(hv[0], hv[1]);
    }
    if (t == TSTEPS - 1) {
#pragma unroll
        for (int v = 0; v < 2; ++v) {
            out[OUTN + l * 131072 + n * 1024 + blk * 4 + uh * 2 + v]       = hv[v];
            out[OUTN + l * 131072 + n * 1024 + 512 + blk * 4 + uh * 2 + v] = creg[v];
        }
    }
    __syncthreads();   // protect zsh for next phase
}

// ---- main persistent kernel ------------------------------------------------
__global__ void __launch_bounds__(NTHR, 1) lstm_tc(
    const float* __restrict__ hxs, const float* __restrict__ masks,
    const float* __restrict__ W_ih, const float* __restrict__ W_hh,
    const float* __restrict__ b_ih, const float* __restrict__ b_hh,
    float* __restrict__ out)
{
    extern __shared__ __align__(1024) char sm[];
    uint32_t smb = (uint32_t)__cvta_generic_to_shared(sm);
    int tid = threadIdx.x, blk = blockIdx.x;

    // weight conversion: l=0 -> recurrent only (sg 0..31); l=1 full (sg 0..63)
    unsigned short* bw = (unsigned short*)(sm + SM_W);
    for (int idx = tid; idx < 2 * 16 * 1024; idx += NTHR) {
        int l = idx >> 14, col = (idx >> 10) & 15, k = idx & 1023;
        if (l == 0 && k < 512) continue;
        int grow = (col >> 2) * 512 + blk * 4 + (col & 3);
        float wv = (k < 512)
            ? W_ih[((size_t)l * 2048 + grow) * 512 + k]
            : W_hh[((size_t)l * 2048 + grow) * 512 + (k - 512)];
        unsigned short hi, lo;
        h2split(wv, hi, lo);
        int sg = (l == 0) ? ((k - 512) >> 4) : (k >> 4);
        int kk = k & 15;
        int reg = (kk >> 3) & 1, pos = kk & 1;
        int lamd = (col & 7) * 4 + ((kk & 7) >> 1);
        int nt = col >> 3;
        int base = (((l * 2 + 0) * 64 + sg) * 2 + nt) * 128 + lamd * 4 + reg * 2 + pos;
        bw[base] = hi;
        bw[base + 64 * 2 * 128] = lo;
    }
    if (tid < 32) {
        int l = tid >> 4, c = tid & 15;
        int grow = (c >> 2) * 512 + blk * 4 + (c & 3);
        ((float*)(sm + SM_BIAS))[tid] = b_ih[l * 2048 + grow] + b_hh[l * 2048 + grow];
    }

    // init masked h state (pp=0) from hxs * masks[0]
    for (int idx = blk * NTHR + tid; idx < 2 * 65536; idx += NBLK * NTHR) {
        int l = idx >> 16, r = idx & 65535;
        int n = r >> 9, jj = r & 511;
        float v = hxs[(size_t)l * 131072 + n * 1024 + jj] * __ldg(masks + n);
        stcg16(&g_hst[l][0][r], __half_as_ushort(__float2half_rn(v)));
    }
    // init c in registers (thread owns 2 units per layer)
    int n0 = tid & 127, uh0 = tid >> 7;
    float creg[2][2];
#pragma unroll
    for (int l = 0; l < 2; ++l)
#pragma unroll
        for (int v = 0; v < 2; ++v)
            creg[l][v] = hxs[(size_t)l * 131072 + n0 * 1024 + 512 + blk * 4 + uh0 * 2 + v];

    grid_barrier();

#pragma unroll 1
    for (int t = 0; t < TSTEPS; ++t) {
        int pr = t & 1, pw = pr ^ 1, mb = t & 1;
        // layer 0: A = masked h0_prev (K=512); x-part preloaded from g_z0x
        phase(0, t, blk, 8,
              g_hst[0][pr], g_hst[0][pr],
              g_z0x + (size_t)t * 2048 * 128,
              g_hst[0][pw], g_mid[mb],
              sm, smb, creg[0], masks, out);
        grid_barrier();
        // layer 1: A = [h0_new unmasked ; masked h1_prev] (K=1024)
        phase(1, t, blk, 16,
              g_mid[mb], g_hst[1][pr],
              nullptr,
              g_hst[1][pw], nullptr,
              sm, smb, creg[1], masks, out);
    }
}

// ---- x0gemm: Z0x[t] = x_t @ W_ih0^T (all t, fully parallel) ----------------
__global__ void __launch_bounds__(256, 1) x0gemm(const float* __restrict__ W_ih) {
    extern __shared__ __align__(1024) char sm[];
    uint32_t smb = (uint32_t)__cvta_generic_to_shared(sm);
    uint32_t abase = smb + XW_BYTES;
    int tid = threadIdx.x, w = tid >> 5, lane = tid & 31;
    int sub = lane >> 3, lrow = lane & 7;
    int bc = blockIdx.x, tg = blockIdx.y;

    // convert W_ih layer0: 64 cols (4 gates x units bc*16..+16), K=512
    unsigned short* bw = (unsigned short*)sm;
    for (int idx = tid; idx < 64 * 512; idx += 256) {
        int cidx = idx >> 9, k = idx & 511;
        int gate = cidx >> 4, up = cidx & 15;
        int grow = gate * 512 + bc * 16 + up;
        float wv = W_ih[(size_t)grow * 512 + k];
        unsigned short hi, lo;
        h2split(wv, hi, lo);
        int sg = k >> 4, kk = k & 15;
        int reg = (kk >> 3) & 1, pos = kk & 1;
        int lamd = (cidx & 7) * 4 + ((kk & 7) >> 1);
        int nt = cidx >> 3;
        int base = (sg * 8 + nt) * 128 + lamd * 4 + reg * 2 + pos;
        bw[base] = hi;
        bw[base + 32 * 8 * 128] = lo;
    }
    __syncthreads();
    const uint2* bf = (const uint2*)sm;

#pragma unroll 1
    for (int tt = 0; tt < 16; ++tt) {
        int t = tg * 16 + tt;
        const __half* xs = g_x + (size_t)t * 65536;

#pragma unroll
        for (int c = 0; c < 4; ++c) { stage_w(xs, xs, c, abase, w, lane); cp_commit(); }

        float acc[8][4] = {};
#pragma unroll 1
        for (int i = 0; i < 8; ++i) {
            cp_wait<3>();
            uint32_t ab = abase + (i & 3) * 16384;
#pragma unroll
            for (int ks = 0; ks < 4; ++ks) {
                uint32_t Ah[4];
                int r = w * 16 + ((sub & 1) << 3) + lrow;
                uint32_t aoff = r * 128 + (((2 * ks + (sub >> 1)) ^ (r & 7)) << 4);
                ldm4(Ah, ab + aoff);
                int sg = i * 4 + ks;
#pragma unroll
                for (int nt = 0; nt < 8; ++nt) {
                    uint2 Bh = bf[(sg * 8 + nt) * 32 + lane];
                    uint2 Bl = bf[((32 + sg) * 8 + nt) * 32 + lane];
                    mma(acc[nt], Ah, Bh.x, Bh.y);
                    mma(acc[nt], Ah, Bl.x, Bl.y);
                }
            }
            if (i + 4 < 8) stage_w(xs, xs, i + 4, abase, w, lane);
            cp_commit();
        }

        // write Z0x fragments: [t][c_g][n(m)]
        float* Z = g_z0x + (size_t)t * 2048 * 128;
        int m0 = w * 16 + (lane >> 2);
#pragma unroll
        for (int nt = 0; nt < 8; ++nt) {
            int c0 = nt * 8 + (lane & 3) * 2, c1 = c0 + 1;
            int cg0 = (c0 >> 4) * 512 + bc * 16 + (c0 & 15);
            int cg1 = (c1 >> 4) * 512 + bc * 16 + (c1 & 15);
            __stcg(Z + (size_t)cg0 * 128 + m0,     acc[nt][0]);
            __stcg(Z + (size_t)cg1 * 128 + m0,     acc[nt][1]);
            __stcg(Z + (size_t)cg0 * 128 + m0 + 8, acc[nt][2]);
            __stcg(Z + (size_t)cg1 * 128 + m0 + 8, acc[nt][3]);
        }
    }
}

// ---- x -> fp16 -------------------------------------------------------------
__global__ void __launch_bounds__(256) xconv(const float* __restrict__ x) {
    size_t i = (size_t)blockIdx.x * 256 + threadIdx.x;
    if (i >= (size_t)OUTN / 4) return;
    float4 v = __ldg(((const float4*)x) + i);
    unsigned short h0 = __half_as_ushort(__float2half_rn(v.x));
    unsigned short h1 = __half_as_ushort(__float2half_rn(v.y));
    unsigned short h2 = __half_as_ushort(__float2half_rn(v.z));
    unsigned short h3 = __half_as_ushort(__float2half_rn(v.w));
    *(uint2*)(g_x + i * 4) = make_uint2(h0 | ((uint32_t)h1 << 16),
                                        h2 | ((uint32_t)h3 << 16));
}

// ---- LayerNorm -------------------------------------------------------------
__global__ void __launch_bounds__(256) ln_kernel(float* __restrict__ out,
                                                 const float* __restrict__ gamma,
                                                 const float* __restrict__ beta)
{
    int lane = threadIdx.x & 31;
    int row  = blockIdx.x * 8 + (threadIdx.x >> 5);
    float* p = out + (size_t)row * 512;
    float4 v[4];
    float s = 0.f, sq = 0.f;
#pragma unroll
    for (int k = 0; k < 4; ++k) {
        v[k] = ((const float4*)p)[(k << 5) + lane];
        s += v[k].x + v[k].y + v[k].z + v[k].w;
        sq = fmaf(v[k].x, v[k].x, sq); sq = fmaf(v[k].y, v[k].y, sq);
        sq = fmaf(v[k].z, v[k].z, sq); sq = fmaf(v[k].w, v[k].w, sq);
    }
#pragma unroll
    for (int o = 16; o; o >>= 1) {
        s  += __shfl_xor_sync(0xffffffffu, s,  o);
        sq += __shfl_xor_sync(0xffffffffu, sq, o);
    }
    float mean = s * (1.0f / 512.0f);
    float inv  = rsqrtf(sq * (1.0f / 512.0f) - mean * mean + 1e-5f);
#pragma unroll
    for (int k = 0; k < 4; ++k) {
        float4 gm = ((const float4*)gamma)[(k << 5) + lane];
        float4 bt = ((const float4*)beta)[(k << 5) + lane];
        float4 r;
        r.x = (v[k].x - mean) * inv * gm.x + bt.x;
        r.y = (v[k].y - mean) * inv * gm.y + bt.y;
        r.z = (v[k].z - mean) * inv * gm.z + bt.z;
        r.w = (v[k].w - mean) * inv * gm.w + bt.w;
        ((float4*)p)[(k << 5) + lane] = r;
    }
}

// ---------------------------------------------------------------------------
extern "C" void kernel_launch(void* const* d_in, const int* in_sizes, int n_in,
                              void* d_out, int out_size) {
    const float* x     = (const float*)d_in[0];
    const float* hxs   = (const float*)d_in[1];
    const float* masks = (const float*)d_in[2];
    const float* W_ih  = (const float*)d_in[3];
    const float* W_hh  = (const float*)d_in[4];
    const float* b_ih  = (const float*)d_in[5];
    const float* b_hh  = (const float*)d_in[6];
    const float* gamma = (const float*)d_in[7];
    const float* beta  = (const float*)d_in[8];
    float* out = (float*)d_out;

    cudaFuncSetAttribute(lstm_tc, cudaFuncAttributeMaxDynamicSharedMemorySize, SM_TOT);
    cudaFuncSetAttribute(x0gemm,  cudaFuncAttributeMaxDynamicSharedMemorySize, X0_TOT);

    xconv<<<(OUTN / 4 + 255) / 256, 256>>>(x);
    x0gemm<<<dim3(32, 32), 256, X0_TOT>>>(W_ih);
    lstm_tc<<<NBLK, NTHR, SM_TOT>>>(hxs, masks, W_ih, W_hh, b_ih, b_hh, out);
    ln_kernel<<<65536 / 8, 256>>>(out, gamma, beta);
}